// round 13
// baseline (speedup 1.0000x reference)
#include <cuda_runtime.h>
#include <cuda_bf16.h>
#include <cstdint>

#define N_NODES 50000
#define N_EDGES 800000
#define D 128

// ---- scratch (device globals; no allocations allowed) ----
__device__ float g_tl[(size_t)N_NODES * D];   // left projection (to aggregate)
__device__ float g_tr[(size_t)N_NODES * D];   // right projection (+bias)
__device__ float g_h[(size_t)N_NODES * D];    // layer output
__device__ int   g_degi[N_NODES];
__device__ int   g_cursor[N_NODES];
__device__ int   g_start[N_NODES + 1];
__device__ int   g_csr_src[N_EDGES];

// ================= CSR build =================
__global__ void zero_kernel() {
    int i = blockIdx.x * blockDim.x + threadIdx.x;
    if (i < N_NODES) { g_degi[i] = 0; g_cursor[i] = 0; }
}
__global__ void count_kernel(const int* __restrict__ dst) {
    int e = blockIdx.x * blockDim.x + threadIdx.x;
    if (e < N_EDGES) atomicAdd(&g_degi[dst[e]], 1);
}

// exclusive scan: serial-per-thread + shuffle block scan (1 block, 1024 thr)
__global__ void scan_kernel() {
    constexpr int PER = (N_NODES + 1023) / 1024;  // 49
    __shared__ int wsum[32];
    int t = threadIdx.x;
    int lane = t & 31, wid = t >> 5;
    int base = t * PER;

    int s = 0;
#pragma unroll 7
    for (int j = 0; j < PER; j++) {
        int i = base + j;
        if (i < N_NODES) s += g_degi[i];
    }
    int v = s;
#pragma unroll
    for (int o = 1; o < 32; o <<= 1) {
        int u = __shfl_up_sync(0xFFFFFFFFu, v, o);
        if (lane >= o) v += u;
    }
    if (lane == 31) wsum[wid] = v;
    __syncthreads();
    if (wid == 0) {
        int w = wsum[lane];
#pragma unroll
        for (int o = 1; o < 32; o <<= 1) {
            int u = __shfl_up_sync(0xFFFFFFFFu, w, o);
            if (lane >= o) w += u;
        }
        wsum[lane] = w;
    }
    __syncthreads();
    int run = (v - s) + (wid > 0 ? wsum[wid - 1] : 0);
#pragma unroll 7
    for (int j = 0; j < PER; j++) {
        int i = base + j;
        if (i < N_NODES) {
            int d = g_degi[i];
            g_start[i] = run;
            run += d;
        }
    }
    if (t == 1023) g_start[N_NODES] = run;
}

__global__ void fill_kernel(const int* __restrict__ src, const int* __restrict__ dst) {
    int e = blockIdx.x * blockDim.x + threadIdx.x;
    if (e < N_EDGES) {
        int d = dst[e];
        int pos = g_start[d] + atomicAdd(&g_cursor[d], 1);
        g_csr_src[pos] = src[e];
    }
}

// ====== fused finish: out = relu(mean-agg(tl) + tr), one warp per node ======
template <int DIMS>
__global__ void aggfin_kernel(const float* __restrict__ tl, const float* __restrict__ tr,
                              float* __restrict__ out) {
    constexpr int NV4 = DIMS / 4;
    int w = (blockIdx.x * blockDim.x + threadIdx.x) >> 5;
    int lane = threadIdx.x & 31;
    if (w >= N_NODES) return;
    bool act = lane < NV4;
    int col = lane * 4;
    int s0 = g_start[w], s1 = g_start[w + 1];
    float4 acc = make_float4(0.f, 0.f, 0.f, 0.f);
    int i = s0;
    for (; i + 4 <= s1; i += 4) {
        int a0 = g_csr_src[i + 0], a1 = g_csr_src[i + 1];
        int a2 = g_csr_src[i + 2], a3 = g_csr_src[i + 3];
        if (act) {
            float4 v0 = *(const float4*)(tl + (size_t)a0 * DIMS + col);
            float4 v1 = *(const float4*)(tl + (size_t)a1 * DIMS + col);
            float4 v2 = *(const float4*)(tl + (size_t)a2 * DIMS + col);
            float4 v3 = *(const float4*)(tl + (size_t)a3 * DIMS + col);
            acc.x += (v0.x + v1.x) + (v2.x + v3.x);
            acc.y += (v0.y + v1.y) + (v2.y + v3.y);
            acc.z += (v0.z + v1.z) + (v2.z + v3.z);
            acc.w += (v0.w + v1.w) + (v2.w + v3.w);
        }
    }
    for (; i < s1; i++) {
        int a = g_csr_src[i];
        if (act) {
            float4 v = *(const float4*)(tl + (size_t)a * DIMS + col);
            acc.x += v.x; acc.y += v.y; acc.z += v.z; acc.w += v.w;
        }
    }
    if (act) {
        float dinv = 1.f / fmaxf((float)(s1 - s0), 1.f);
        float4 t = *(const float4*)(tr + (size_t)w * DIMS + col);
        float4 o;
        o.x = fmaxf(acc.x * dinv + t.x, 0.f);
        o.y = fmaxf(acc.y * dinv + t.y, 0.f);
        o.z = fmaxf(acc.z * dinv + t.z, 0.f);
        o.w = fmaxf(acc.w * dinv + t.w, 0.f);
        *(float4*)(out + (size_t)w * DIMS + col) = o;
    }
}

// ================= split-bf16 projection GEMM (mma.sync + ldmatrix) =================
// grid.y=0: out_l = A @ wl ; grid.y=1: out_r = A @ wr + bias. K=128 (2 chunks). No relu.
#define MMA16816(d, a, b) \
    asm volatile("mma.sync.aligned.m16n8k16.row.col.f32.bf16.bf16.f32 " \
                 "{%0,%1,%2,%3},{%4,%5,%6,%7},{%8,%9},{%0,%1,%2,%3};" \
                 : "+f"((d)[0]), "+f"((d)[1]), "+f"((d)[2]), "+f"((d)[3]) \
                 : "r"((a)[0]), "r"((a)[1]), "r"((a)[2]), "r"((a)[3]), \
                   "r"((b)[0]), "r"((b)[1]))

#define LDMX4(r, a) \
    asm volatile("ldmatrix.sync.aligned.m8n8.x4.shared.b16 {%0,%1,%2,%3}, [%4];" \
                 : "=r"((r)[0]), "=r"((r)[1]), "=r"((r)[2]), "=r"((r)[3]) : "r"(a))

__device__ __forceinline__ uint32_t smem_u32(const void* p) {
    uint32_t a;
    asm("{ .reg .u64 t; cvta.to.shared.u64 t, %1; cvt.u32.u64 %0, t; }" : "=r"(a) : "l"(p));
    return a;
}

template <int BN>
__global__ void __launch_bounds__(256, 1)
gemm_proj_kernel(const float* __restrict__ A,
                 const float* __restrict__ wl, const float* __restrict__ wr,
                 const float* __restrict__ bias,
                 float* __restrict__ out_l, float* __restrict__ out_r, int dout) {
    extern __shared__ char smem[];
    constexpr int PITCH = 72;
    constexpr int A_HI = 0;
    constexpr int A_LO = 128 * PITCH * 2;
    constexpr int B_HI = 2 * 128 * PITCH * 2;
    constexpr int B_LO = B_HI + BN * PITCH * 2;
    constexpr int NFRAG = BN / 32;
    constexpr int G4 = BN / 4;
    constexpr int BITER = BN / 16;

    const float* wsrc = blockIdx.y ? wr : wl;
    float* dst = blockIdx.y ? out_r : out_l;
    bool addb = (blockIdx.y != 0);

    int tid = threadIdx.x, wid = tid >> 5, lane = tid & 31;
    int g = lane >> 2, tig = lane & 3;
    int warp_m = wid & 1, warp_n = wid >> 1;
    int row0 = blockIdx.x * 128;
    uint32_t sb = smem_u32(smem);

    float acc[4][NFRAG][4];
#pragma unroll
    for (int m = 0; m < 4; m++)
#pragma unroll
        for (int nf = 0; nf < NFRAG; nf++)
#pragma unroll
            for (int j = 0; j < 4; j++) acc[m][nf][j] = 0.f;

    int a_row = warp_m * 64 + (lane & 15);
    int a_kof = (lane >> 4) << 3;
    int b_n0  = warp_n * (BN / 4) + ((lane >> 3) & 1) * 8 + (lane & 7);
    int b_kof = (lane >> 4) << 3;

    float4 pa[8];
    // prefetch chunk 0 (k 0..63)
#pragma unroll
    for (int j = 0; j < 8; j++) {
        int i = tid + j * 256;
        int r = i >> 4, kq = (i & 15) << 2;
        int row = row0 + r;
        pa[j] = (row < N_NODES) ? *(const float4*)(A + (size_t)row * D + kq)
                                : make_float4(0.f, 0.f, 0.f, 0.f);
    }

    for (int ch = 0; ch < 2; ch++) {
        int koff = ch * 64;
        __syncthreads();

        // convert prefetched A regs -> smem hi/lo
#pragma unroll
        for (int j = 0; j < 8; j++) {
            int i = tid + j * 256;
            int r = i >> 4, kq = (i & 15) << 2;
            float4 v = pa[j];
            __nv_bfloat16 h0 = __float2bfloat16(v.x), h1 = __float2bfloat16(v.y);
            __nv_bfloat16 h2 = __float2bfloat16(v.z), h3 = __float2bfloat16(v.w);
            __nv_bfloat16 l0 = __float2bfloat16(v.x - __bfloat162float(h0));
            __nv_bfloat16 l1 = __float2bfloat16(v.y - __bfloat162float(h1));
            __nv_bfloat16 l2 = __float2bfloat16(v.z - __bfloat162float(h2));
            __nv_bfloat16 l3 = __float2bfloat16(v.w - __bfloat162float(h3));
            uint2 hp, lp;
            hp.x = (uint32_t)__bfloat16_as_ushort(h0) | ((uint32_t)__bfloat16_as_ushort(h1) << 16);
            hp.y = (uint32_t)__bfloat16_as_ushort(h2) | ((uint32_t)__bfloat16_as_ushort(h3) << 16);
            lp.x = (uint32_t)__bfloat16_as_ushort(l0) | ((uint32_t)__bfloat16_as_ushort(l1) << 16);
            lp.y = (uint32_t)__bfloat16_as_ushort(l2) | ((uint32_t)__bfloat16_as_ushort(l3) << 16);
            int off = (r * PITCH + kq) * 2;
            *(uint2*)(smem + A_HI + off) = hp;
            *(uint2*)(smem + A_LO + off) = lp;
        }
        // B tile: BN n-rows x 64 k (transpose from w[k][n], hi/lo)
#pragma unroll
        for (int j = 0; j < BITER; j++) {
            int i = tid + j * 256;
            int k = i / G4;
            int n4 = (i - k * G4) * 4;
            float4 v = make_float4(0.f, 0.f, 0.f, 0.f);
            if (n4 + 4 <= dout) v = *(const float4*)(wsrc + (size_t)(koff + k) * dout + n4);
            float fx[4] = {v.x, v.y, v.z, v.w};
#pragma unroll
            for (int jj = 0; jj < 4; jj++) {
                __nv_bfloat16 h = __float2bfloat16(fx[jj]);
                __nv_bfloat16 l = __float2bfloat16(fx[jj] - __bfloat162float(h));
                int off = ((n4 + jj) * PITCH + k) * 2;
                *(__nv_bfloat16*)(smem + B_HI + off) = h;
                *(__nv_bfloat16*)(smem + B_LO + off) = l;
            }
        }
        __syncthreads();

        // prefetch next chunk's A (k 64..127) under MMA
        if (ch == 0) {
#pragma unroll
            for (int j = 0; j < 8; j++) {
                int i = tid + j * 256;
                int r = i >> 4, kq = (i & 15) << 2;
                int row = row0 + r;
                pa[j] = (row < N_NODES) ? *(const float4*)(A + (size_t)row * D + 64 + kq)
                                        : make_float4(0.f, 0.f, 0.f, 0.f);
            }
        }

        // MMA: 4 k16 steps x (hi*hi + hi*lo + lo*hi)
#pragma unroll
        for (int ks = 0; ks < 4; ks++) {
            int kb = ks * 16;
            uint32_t ahi[4][4], alo[4][4];
#pragma unroll
            for (int m = 0; m < 4; m++) {
                uint32_t ao = sb + (uint32_t)(((a_row + m * 16) * PITCH + kb + a_kof) * 2);
                LDMX4(ahi[m], ao + A_HI);
                LDMX4(alo[m], ao + A_LO);
            }
            uint32_t bhi[NFRAG][2], blo[NFRAG][2];
#pragma unroll
            for (int p = 0; p < NFRAG / 2; p++) {
                uint32_t bo = sb + (uint32_t)(((b_n0 + p * 16) * PITCH + kb + b_kof) * 2);
                uint32_t rh[4], rl[4];
                LDMX4(rh, bo + B_HI);
                LDMX4(rl, bo + B_LO);
                bhi[2 * p][0] = rh[0]; bhi[2 * p + 1][0] = rh[1];
                bhi[2 * p][1] = rh[2]; bhi[2 * p + 1][1] = rh[3];
                blo[2 * p][0] = rl[0]; blo[2 * p + 1][0] = rl[1];
                blo[2 * p][1] = rl[2]; blo[2 * p + 1][1] = rl[3];
            }
#pragma unroll
            for (int m = 0; m < 4; m++)
#pragma unroll
                for (int nf = 0; nf < NFRAG; nf++) {
                    MMA16816(acc[m][nf], ahi[m], bhi[nf]);
                    MMA16816(acc[m][nf], ahi[m], blo[nf]);
                    MMA16816(acc[m][nf], alo[m], bhi[nf]);
                }
        }
    }

    // epilogue: optional bias, NO relu (relu happens after aggregation)
#pragma unroll
    for (int m = 0; m < 4; m++) {
        int row = row0 + warp_m * 64 + m * 16 + g;
#pragma unroll
        for (int nf = 0; nf < NFRAG; nf++) {
            int col = warp_n * (BN / 4) + nf * 8 + 2 * tig;
            if (col < dout) {
                float bc0 = addb ? bias[col] : 0.f;
                float bc1 = addb ? bias[col + 1] : 0.f;
                if (row < N_NODES) {
                    dst[(size_t)row * dout + col]     = acc[m][nf][0] + bc0;
                    dst[(size_t)row * dout + col + 1] = acc[m][nf][1] + bc1;
                }
                if (row + 8 < N_NODES) {
                    dst[(size_t)(row + 8) * dout + col]     = acc[m][nf][2] + bc0;
                    dst[(size_t)(row + 8) * dout + col + 1] = acc[m][nf][3] + bc1;
                }
            }
        }
    }
}

// ================= launch =================
extern "C" void kernel_launch(void* const* d_in, const int* in_sizes, int n_in,
                              void* d_out, int out_size) {
    const float* x = (const float*)d_in[0];
    const int* ei = (const int*)d_in[1];   // edge_index is int32 on device
    const int* src = ei;
    const int* dst = ei + N_EDGES;
    const float* w1l = (const float*)d_in[2];
    const float* w1r = (const float*)d_in[3];
    const float* b1  = (const float*)d_in[4];
    const float* w2l = (const float*)d_in[5];
    const float* w2r = (const float*)d_in[6];
    const float* b2  = (const float*)d_in[7];
    const float* w3l = (const float*)d_in[8];
    const float* w3r = (const float*)d_in[9];
    const float* b3  = (const float*)d_in[10];
    float* out = (float*)d_out;

    void *p_tl, *p_tr, *p_h;
    cudaGetSymbolAddress(&p_tl, g_tl);
    cudaGetSymbolAddress(&p_tr, g_tr);
    cudaGetSymbolAddress(&p_h, g_h);
    float* tl = (float*)p_tl;
    float* tr = (float*)p_tr;
    float* h  = (float*)p_h;

    const int SMEM128 = 2 * 128 * 72 * 2 + 2 * 128 * 72 * 2;  // 73728
    const int SMEM64  = 2 * 128 * 72 * 2 + 2 * 64 * 72 * 2;   // 55296

    static bool s_init = false;
    static cudaStream_t s2;
    static cudaEvent_t evA, evB;
    if (!s_init) {
        cudaFuncSetAttribute(gemm_proj_kernel<128>, cudaFuncAttributeMaxDynamicSharedMemorySize, SMEM128);
        cudaFuncSetAttribute(gemm_proj_kernel<64>,  cudaFuncAttributeMaxDynamicSharedMemorySize, SMEM64);
        cudaStreamCreateWithFlags(&s2, cudaStreamNonBlocking);
        cudaEventCreateWithFlags(&evA, cudaEventDisableTiming);
        cudaEventCreateWithFlags(&evB, cudaEventDisableTiming);
        s_init = true;
    }

    int nb = (N_NODES + 255) / 256;
    int eb = (N_EDGES + 255) / 256;
    int gb = (N_NODES + 127) / 128;
    int ab = (N_NODES * 32 + 255) / 256;
    dim3 gproj(gb, 2);

    // fork: layer-1 projection (depends only on x) runs concurrently with CSR build
    cudaEventRecord(evA, 0);
    cudaStreamWaitEvent(s2, evA, 0);
    gemm_proj_kernel<128><<<gproj, 256, SMEM128, s2>>>(x, w1l, w1r, b1, tl, tr, 128);
    cudaEventRecord(evB, s2);

    // CSR build on main stream
    zero_kernel<<<nb, 256>>>();
    count_kernel<<<eb, 256>>>(dst);
    scan_kernel<<<1, 1024>>>();
    fill_kernel<<<eb, 256>>>(src, dst);

    // join
    cudaStreamWaitEvent(0, evB, 0);

    // layer 1 finish: h1 = relu(agg(tl) + tr)
    aggfin_kernel<128><<<ab, 256>>>(tl, tr, h);
    // layer 2
    gemm_proj_kernel<128><<<gproj, 256, SMEM128>>>(h, w2l, w2r, b2, tl, tr, 128);
    aggfin_kernel<128><<<ab, 256>>>(tl, tr, h);
    // layer 3 (40-dim aggregation)
    gemm_proj_kernel<64><<<gproj, 256, SMEM64>>>(h, w3l, w3r, b3, tl, tr, 40);
    aggfin_kernel<40><<<ab, 256>>>(tl, tr, out);
}

// round 14
// speedup vs baseline: 1.1074x; 1.1074x over previous
#include <cuda_runtime.h>
#include <cuda_bf16.h>
#include <cstdint>

#define N_NODES 50000
#define N_EDGES 800000
#define D 128
#define SCAN_BLK 256
#define SCAN_NBLK ((N_NODES + SCAN_BLK - 1) / SCAN_BLK)   // 196

// ---- scratch (device globals; no allocations allowed) ----
__device__ float g_tl[(size_t)N_NODES * D];   // left projection (to aggregate)
__device__ float g_tr[(size_t)N_NODES * D];   // right projection (+bias)
__device__ float g_h[(size_t)N_NODES * D];    // layer output
__device__ int   g_degi[N_NODES];
__device__ int   g_cursor[N_NODES];
__device__ int   g_start[N_NODES + 1];
__device__ int   g_csr_src[N_EDGES];
__device__ int   g_bsum[SCAN_NBLK];
__device__ int   g_boff[SCAN_NBLK];

// ================= CSR build =================
__global__ void zero_kernel() {
    int i = blockIdx.x * blockDim.x + threadIdx.x;
    if (i < N_NODES) { g_degi[i] = 0; g_cursor[i] = 0; }
}
__global__ void count_kernel(const int* __restrict__ dst) {
    int e = blockIdx.x * blockDim.x + threadIdx.x;
    if (e < N_EDGES) atomicAdd(&g_degi[dst[e]], 1);
}

// ---- multi-block exclusive scan over g_degi -> g_start ----
__global__ void scan_pass1() {
    int t = threadIdx.x, lane = t & 31, wid = t >> 5;
    int i = blockIdx.x * SCAN_BLK + t;
    int v = (i < N_NODES) ? g_degi[i] : 0;
#pragma unroll
    for (int o = 16; o > 0; o >>= 1) v += __shfl_down_sync(0xFFFFFFFFu, v, o);
    __shared__ int ws[8];
    if (lane == 0) ws[wid] = v;
    __syncthreads();
    if (wid == 0) {
        int s = (lane < 8) ? ws[lane] : 0;
#pragma unroll
        for (int o = 4; o > 0; o >>= 1) s += __shfl_down_sync(0xFFFFFFFFu, s, o);
        if (lane == 0) g_bsum[blockIdx.x] = s;
    }
}
__global__ void scan_pass2() {
    int t = threadIdx.x, lane = t & 31, wid = t >> 5;
    int v = (t < SCAN_NBLK) ? g_bsum[t] : 0;
    int inc = v;
#pragma unroll
    for (int o = 1; o < 32; o <<= 1) {
        int u = __shfl_up_sync(0xFFFFFFFFu, inc, o);
        if (lane >= o) inc += u;
    }
    __shared__ int ws[8];
    if (lane == 31) ws[wid] = inc;
    __syncthreads();
    if (wid == 0) {
        int s = (lane < 8) ? ws[lane] : 0;
#pragma unroll
        for (int o = 1; o < 8; o <<= 1) {
            int u = __shfl_up_sync(0xFFFFFFFFu, s, o);
            if (lane >= o) s += u;
        }
        if (lane < 8) ws[lane] = s;
    }
    __syncthreads();
    int excl = inc - v + (wid > 0 ? ws[wid - 1] : 0);
    if (t < SCAN_NBLK) g_boff[t] = excl;
}
__global__ void scan_pass3() {
    int t = threadIdx.x, lane = t & 31, wid = t >> 5;
    int i = blockIdx.x * SCAN_BLK + t;
    int d = (i < N_NODES) ? g_degi[i] : 0;
    int inc = d;
#pragma unroll
    for (int o = 1; o < 32; o <<= 1) {
        int u = __shfl_up_sync(0xFFFFFFFFu, inc, o);
        if (lane >= o) inc += u;
    }
    __shared__ int ws[8];
    if (lane == 31) ws[wid] = inc;
    __syncthreads();
    if (wid == 0) {
        int s = (lane < 8) ? ws[lane] : 0;
#pragma unroll
        for (int o = 1; o < 8; o <<= 1) {
            int u = __shfl_up_sync(0xFFFFFFFFu, s, o);
            if (lane >= o) s += u;
        }
        if (lane < 8) ws[lane] = s;
    }
    __syncthreads();
    int excl = inc - d + (wid > 0 ? ws[wid - 1] : 0) + g_boff[blockIdx.x];
    if (i < N_NODES) g_start[i] = excl;
    if (i == N_NODES - 1) g_start[N_NODES] = excl + d;
}

__global__ void fill_kernel(const int* __restrict__ src, const int* __restrict__ dst) {
    int e = blockIdx.x * blockDim.x + threadIdx.x;
    if (e < N_EDGES) {
        int d = dst[e];
        int pos = g_start[d] + atomicAdd(&g_cursor[d], 1);
        g_csr_src[pos] = src[e];
    }
}

// ====== fused finish: out = relu(mean-agg(tl) + tr), one warp per node ======
template <int DIMS>
__global__ void aggfin_kernel(const float* __restrict__ tl, const float* __restrict__ tr,
                              float* __restrict__ out) {
    constexpr int NV4 = DIMS / 4;
    int w = (blockIdx.x * blockDim.x + threadIdx.x) >> 5;
    int lane = threadIdx.x & 31;
    if (w >= N_NODES) return;
    bool act = lane < NV4;
    int col = lane * 4;
    int s0 = g_start[w], s1 = g_start[w + 1];
    float4 acc = make_float4(0.f, 0.f, 0.f, 0.f);
    int i = s0;
    for (; i + 4 <= s1; i += 4) {
        int a0 = g_csr_src[i + 0], a1 = g_csr_src[i + 1];
        int a2 = g_csr_src[i + 2], a3 = g_csr_src[i + 3];
        if (act) {
            float4 v0 = *(const float4*)(tl + (size_t)a0 * DIMS + col);
            float4 v1 = *(const float4*)(tl + (size_t)a1 * DIMS + col);
            float4 v2 = *(const float4*)(tl + (size_t)a2 * DIMS + col);
            float4 v3 = *(const float4*)(tl + (size_t)a3 * DIMS + col);
            acc.x += (v0.x + v1.x) + (v2.x + v3.x);
            acc.y += (v0.y + v1.y) + (v2.y + v3.y);
            acc.z += (v0.z + v1.z) + (v2.z + v3.z);
            acc.w += (v0.w + v1.w) + (v2.w + v3.w);
        }
    }
    for (; i < s1; i++) {
        int a = g_csr_src[i];
        if (act) {
            float4 v = *(const float4*)(tl + (size_t)a * DIMS + col);
            acc.x += v.x; acc.y += v.y; acc.z += v.z; acc.w += v.w;
        }
    }
    if (act) {
        float dinv = 1.f / fmaxf((float)(s1 - s0), 1.f);
        float4 t = *(const float4*)(tr + (size_t)w * DIMS + col);
        float4 o;
        o.x = fmaxf(acc.x * dinv + t.x, 0.f);
        o.y = fmaxf(acc.y * dinv + t.y, 0.f);
        o.z = fmaxf(acc.z * dinv + t.z, 0.f);
        o.w = fmaxf(acc.w * dinv + t.w, 0.f);
        *(float4*)(out + (size_t)w * DIMS + col) = o;
    }
}

// ================= split-bf16 projection GEMM (mma.sync + ldmatrix) =================
// grid.y=0: out_l = A @ wl ; grid.y=1: out_r = A @ wr + bias. K=128 (2 chunks). No relu.
#define MMA16816(d, a, b) \
    asm volatile("mma.sync.aligned.m16n8k16.row.col.f32.bf16.bf16.f32 " \
                 "{%0,%1,%2,%3},{%4,%5,%6,%7},{%8,%9},{%0,%1,%2,%3};" \
                 : "+f"((d)[0]), "+f"((d)[1]), "+f"((d)[2]), "+f"((d)[3]) \
                 : "r"((a)[0]), "r"((a)[1]), "r"((a)[2]), "r"((a)[3]), \
                   "r"((b)[0]), "r"((b)[1]))

#define LDMX4(r, a) \
    asm volatile("ldmatrix.sync.aligned.m8n8.x4.shared.b16 {%0,%1,%2,%3}, [%4];" \
                 : "=r"((r)[0]), "=r"((r)[1]), "=r"((r)[2]), "=r"((r)[3]) : "r"(a))

__device__ __forceinline__ uint32_t smem_u32(const void* p) {
    uint32_t a;
    asm("{ .reg .u64 t; cvta.to.shared.u64 t, %1; cvt.u32.u64 %0, t; }" : "=r"(a) : "l"(p));
    return a;
}

template <int BN>
__global__ void __launch_bounds__(256, 1)
gemm_proj_kernel(const float* __restrict__ A,
                 const float* __restrict__ wl, const float* __restrict__ wr,
                 const float* __restrict__ bias,
                 float* __restrict__ out_l, float* __restrict__ out_r, int dout) {
    extern __shared__ char smem[];
    constexpr int PITCH = 72;
    constexpr int A_HI = 0;
    constexpr int A_LO = 128 * PITCH * 2;
    constexpr int B_HI = 2 * 128 * PITCH * 2;
    constexpr int B_LO = B_HI + BN * PITCH * 2;
    constexpr int NFRAG = BN / 32;
    constexpr int G4 = BN / 4;
    constexpr int BITER = BN / 16;

    const float* wsrc = blockIdx.y ? wr : wl;
    float* dst = blockIdx.y ? out_r : out_l;
    bool addb = (blockIdx.y != 0);

    int tid = threadIdx.x, wid = tid >> 5, lane = tid & 31;
    int g = lane >> 2, tig = lane & 3;
    int warp_m = wid & 1, warp_n = wid >> 1;
    int row0 = blockIdx.x * 128;
    uint32_t sb = smem_u32(smem);

    float acc[4][NFRAG][4];
#pragma unroll
    for (int m = 0; m < 4; m++)
#pragma unroll
        for (int nf = 0; nf < NFRAG; nf++)
#pragma unroll
            for (int j = 0; j < 4; j++) acc[m][nf][j] = 0.f;

    int a_row = warp_m * 64 + (lane & 15);
    int a_kof = (lane >> 4) << 3;
    int b_n0  = warp_n * (BN / 4) + ((lane >> 3) & 1) * 8 + (lane & 7);
    int b_kof = (lane >> 4) << 3;

    float4 pa[8];
    // prefetch chunk 0 (k 0..63)
#pragma unroll
    for (int j = 0; j < 8; j++) {
        int i = tid + j * 256;
        int r = i >> 4, kq = (i & 15) << 2;
        int row = row0 + r;
        pa[j] = (row < N_NODES) ? *(const float4*)(A + (size_t)row * D + kq)
                                : make_float4(0.f, 0.f, 0.f, 0.f);
    }

    for (int ch = 0; ch < 2; ch++) {
        int koff = ch * 64;
        __syncthreads();

        // convert prefetched A regs -> smem hi/lo
#pragma unroll
        for (int j = 0; j < 8; j++) {
            int i = tid + j * 256;
            int r = i >> 4, kq = (i & 15) << 2;
            float4 v = pa[j];
            __nv_bfloat16 h0 = __float2bfloat16(v.x), h1 = __float2bfloat16(v.y);
            __nv_bfloat16 h2 = __float2bfloat16(v.z), h3 = __float2bfloat16(v.w);
            __nv_bfloat16 l0 = __float2bfloat16(v.x - __bfloat162float(h0));
            __nv_bfloat16 l1 = __float2bfloat16(v.y - __bfloat162float(h1));
            __nv_bfloat16 l2 = __float2bfloat16(v.z - __bfloat162float(h2));
            __nv_bfloat16 l3 = __float2bfloat16(v.w - __bfloat162float(h3));
            uint2 hp, lp;
            hp.x = (uint32_t)__bfloat16_as_ushort(h0) | ((uint32_t)__bfloat16_as_ushort(h1) << 16);
            hp.y = (uint32_t)__bfloat16_as_ushort(h2) | ((uint32_t)__bfloat16_as_ushort(h3) << 16);
            lp.x = (uint32_t)__bfloat16_as_ushort(l0) | ((uint32_t)__bfloat16_as_ushort(l1) << 16);
            lp.y = (uint32_t)__bfloat16_as_ushort(l2) | ((uint32_t)__bfloat16_as_ushort(l3) << 16);
            int off = (r * PITCH + kq) * 2;
            *(uint2*)(smem + A_HI + off) = hp;
            *(uint2*)(smem + A_LO + off) = lp;
        }
        // B tile: BN n-rows x 64 k (transpose from w[k][n], hi/lo)
#pragma unroll
        for (int j = 0; j < BITER; j++) {
            int i = tid + j * 256;
            int k = i / G4;
            int n4 = (i - k * G4) * 4;
            float4 v = make_float4(0.f, 0.f, 0.f, 0.f);
            if (n4 + 4 <= dout) v = *(const float4*)(wsrc + (size_t)(koff + k) * dout + n4);
            float fx[4] = {v.x, v.y, v.z, v.w};
#pragma unroll
            for (int jj = 0; jj < 4; jj++) {
                __nv_bfloat16 h = __float2bfloat16(fx[jj]);
                __nv_bfloat16 l = __float2bfloat16(fx[jj] - __bfloat162float(h));
                int off = ((n4 + jj) * PITCH + k) * 2;
                *(__nv_bfloat16*)(smem + B_HI + off) = h;
                *(__nv_bfloat16*)(smem + B_LO + off) = l;
            }
        }
        __syncthreads();

        // prefetch next chunk's A (k 64..127) under MMA
        if (ch == 0) {
#pragma unroll
            for (int j = 0; j < 8; j++) {
                int i = tid + j * 256;
                int r = i >> 4, kq = (i & 15) << 2;
                int row = row0 + r;
                pa[j] = (row < N_NODES) ? *(const float4*)(A + (size_t)row * D + 64 + kq)
                                        : make_float4(0.f, 0.f, 0.f, 0.f);
            }
        }

        // MMA: 4 k16 steps x (hi*hi + hi*lo + lo*hi)
#pragma unroll
        for (int ks = 0; ks < 4; ks++) {
            int kb = ks * 16;
            uint32_t ahi[4][4], alo[4][4];
#pragma unroll
            for (int m = 0; m < 4; m++) {
                uint32_t ao = sb + (uint32_t)(((a_row + m * 16) * PITCH + kb + a_kof) * 2);
                LDMX4(ahi[m], ao + A_HI);
                LDMX4(alo[m], ao + A_LO);
            }
            uint32_t bhi[NFRAG][2], blo[NFRAG][2];
#pragma unroll
            for (int p = 0; p < NFRAG / 2; p++) {
                uint32_t bo = sb + (uint32_t)(((b_n0 + p * 16) * PITCH + kb + b_kof) * 2);
                uint32_t rh[4], rl[4];
                LDMX4(rh, bo + B_HI);
                LDMX4(rl, bo + B_LO);
                bhi[2 * p][0] = rh[0]; bhi[2 * p + 1][0] = rh[1];
                bhi[2 * p][1] = rh[2]; bhi[2 * p + 1][1] = rh[3];
                blo[2 * p][0] = rl[0]; blo[2 * p + 1][0] = rl[1];
                blo[2 * p][1] = rl[2]; blo[2 * p + 1][1] = rl[3];
            }
#pragma unroll
            for (int m = 0; m < 4; m++)
#pragma unroll
                for (int nf = 0; nf < NFRAG; nf++) {
                    MMA16816(acc[m][nf], ahi[m], bhi[nf]);
                    MMA16816(acc[m][nf], ahi[m], blo[nf]);
                    MMA16816(acc[m][nf], alo[m], bhi[nf]);
                }
        }
    }

    // epilogue: optional bias, NO relu (relu happens after aggregation)
#pragma unroll
    for (int m = 0; m < 4; m++) {
        int row = row0 + warp_m * 64 + m * 16 + g;
#pragma unroll
        for (int nf = 0; nf < NFRAG; nf++) {
            int col = warp_n * (BN / 4) + nf * 8 + 2 * tig;
            if (col < dout) {
                float bc0 = addb ? bias[col] : 0.f;
                float bc1 = addb ? bias[col + 1] : 0.f;
                if (row < N_NODES) {
                    dst[(size_t)row * dout + col]     = acc[m][nf][0] + bc0;
                    dst[(size_t)row * dout + col + 1] = acc[m][nf][1] + bc1;
                }
                if (row + 8 < N_NODES) {
                    dst[(size_t)(row + 8) * dout + col]     = acc[m][nf][2] + bc0;
                    dst[(size_t)(row + 8) * dout + col + 1] = acc[m][nf][3] + bc1;
                }
            }
        }
    }
}

// ================= launch =================
extern "C" void kernel_launch(void* const* d_in, const int* in_sizes, int n_in,
                              void* d_out, int out_size) {
    const float* x = (const float*)d_in[0];
    const int* ei = (const int*)d_in[1];   // edge_index is int32 on device
    const int* src = ei;
    const int* dst = ei + N_EDGES;
    const float* w1l = (const float*)d_in[2];
    const float* w1r = (const float*)d_in[3];
    const float* b1  = (const float*)d_in[4];
    const float* w2l = (const float*)d_in[5];
    const float* w2r = (const float*)d_in[6];
    const float* b2  = (const float*)d_in[7];
    const float* w3l = (const float*)d_in[8];
    const float* w3r = (const float*)d_in[9];
    const float* b3  = (const float*)d_in[10];
    float* out = (float*)d_out;

    void *p_tl, *p_tr, *p_h;
    cudaGetSymbolAddress(&p_tl, g_tl);
    cudaGetSymbolAddress(&p_tr, g_tr);
    cudaGetSymbolAddress(&p_h, g_h);
    float* tl = (float*)p_tl;
    float* tr = (float*)p_tr;
    float* h  = (float*)p_h;

    const int SMEM128 = 2 * 128 * 72 * 2 + 2 * 128 * 72 * 2;  // 73728
    const int SMEM64  = 2 * 128 * 72 * 2 + 2 * 64 * 72 * 2;   // 55296

    static bool s_init = false;
    static cudaStream_t s2;
    static cudaEvent_t evA, evB;
    if (!s_init) {
        cudaFuncSetAttribute(gemm_proj_kernel<128>, cudaFuncAttributeMaxDynamicSharedMemorySize, SMEM128);
        cudaFuncSetAttribute(gemm_proj_kernel<64>,  cudaFuncAttributeMaxDynamicSharedMemorySize, SMEM64);
        cudaStreamCreateWithFlags(&s2, cudaStreamNonBlocking);
        cudaEventCreateWithFlags(&evA, cudaEventDisableTiming);
        cudaEventCreateWithFlags(&evB, cudaEventDisableTiming);
        s_init = true;
    }

    int nb = (N_NODES + 255) / 256;
    int eb = (N_EDGES + 255) / 256;
    int gb = (N_NODES + 127) / 128;
    int ab = (N_NODES * 32 + 255) / 256;
    dim3 gproj(gb, 2);

    // fork: layer-1 projection (depends only on x) runs concurrently with CSR build
    cudaEventRecord(evA, 0);
    cudaStreamWaitEvent(s2, evA, 0);
    gemm_proj_kernel<128><<<gproj, 256, SMEM128, s2>>>(x, w1l, w1r, b1, tl, tr, 128);
    cudaEventRecord(evB, s2);

    // CSR build on main stream (multi-block scan)
    zero_kernel<<<nb, 256>>>();
    count_kernel<<<eb, 256>>>(dst);
    scan_pass1<<<SCAN_NBLK, SCAN_BLK>>>();
    scan_pass2<<<1, SCAN_BLK>>>();
    scan_pass3<<<SCAN_NBLK, SCAN_BLK>>>();
    fill_kernel<<<eb, 256>>>(src, dst);

    // join
    cudaStreamWaitEvent(0, evB, 0);

    // layer 1 finish: h1 = relu(agg(tl) + tr)
    aggfin_kernel<128><<<ab, 256>>>(tl, tr, h);
    // layer 2
    gemm_proj_kernel<128><<<gproj, 256, SMEM128>>>(h, w2l, w2r, b2, tl, tr, 128);
    aggfin_kernel<128><<<ab, 256>>>(tl, tr, h);
    // layer 3 (40-dim aggregation)
    gemm_proj_kernel<64><<<gproj, 256, SMEM64>>>(h, w3l, w3r, b3, tl, tr, 40);
    aggfin_kernel<40><<<ab, 256>>>(tl, tr, out);
}